// round 2
// baseline (speedup 1.0000x reference)
#include <cuda_runtime.h>

#define G       8      // items (graphs) per CTA
#define NNODE   64
#define FPN     8
#define H       128
#define MODES   8
#define BT      16384  // B*L
#define NTHREADS 256

// -------- persistent scratch (no allocation allowed) --------
__device__ __align__(16) float g_w0t[MODES * H * H];  // [k][i][j]
__device__ __align__(16) float g_w2t[MODES * H * H];  // [k][i][j]
__device__ __align__(16) float g_A8[NNODE * MODES];   // adj @ U[:, :8]
__device__ __align__(16) float g_s[MODES];            // colsum of U[:, :8]

struct SmemLayout {
    float bufA[G][MODES][H];   // xf0 / xf2
    float bufB[G][MODES][H];   // of0 / of2
    float bufP[G][MODES][H];
    float bufQ[G][MODES][H];
    float sX[G][NNODE * FPN];
    float sXS[G][MODES][FPN];
    float sU8[NNODE][MODES];
    float sA8[NNODE][MODES];
    float sWp[FPN * H];
    float sWo[H * FPN];
    float s_bp[H];
    float s_b1[H]; float s_g1[H]; float s_be1[H];
    float s_b3[H]; float s_g3[H]; float s_be3[H];
    float s_s[MODES]; float s_bo[FPN];
};

__device__ __forceinline__ void fma4(float4& a, float s, const float4 b) {
    a.x = fmaf(s, b.x, a.x); a.y = fmaf(s, b.y, a.y);
    a.z = fmaf(s, b.z, a.z); a.w = fmaf(s, b.w, a.w);
}

// ---------------- prep kernels ----------------
__global__ void prep_w(const float* __restrict__ w0, const float* __restrict__ w2) {
    const int total = MODES * H * H;
    for (int o = blockIdx.x * blockDim.x + threadIdx.x; o < total;
         o += gridDim.x * blockDim.x) {
        int k = o >> 14;            // / (H*H)
        int rem = o & 16383;
        int i = rem >> 7;
        int j = rem & 127;
        int src = ((i << 7) + j) * MODES + k;   // w[(i,j,k)]
        g_w0t[o] = w0[src];
        g_w2t[o] = w2[src];
    }
}

__global__ void prep_graph(const float* __restrict__ adj, const float* __restrict__ Uin) {
    int o = threadIdx.x;           // 512 threads
    if (o < NNODE * MODES) {
        int n = o >> 3, k = o & 7;
        float a = 0.f;
        for (int m = 0; m < NNODE; m++) a += adj[n * NNODE + m] * Uin[m * NNODE + k];
        g_A8[o] = a;
    }
    if (o < MODES) {
        float s = 0.f;
        for (int m = 0; m < NNODE; m++) s += Uin[m * NNODE + o];
        g_s[o] = s;
    }
}

// ---------------- fused stages ----------------
// of[g,k,j] = sum_i xf[g,k,i] * wt[k][i][j]     (one warp per mode k)
__device__ __forceinline__ void mode_mix(const float (*xf)[MODES][H],
                                         float (*of)[MODES][H],
                                         const float* __restrict__ wt,
                                         int warp, int lane) {
    const int k = warp;
    const float* wk = wt + k * (H * H);
    const int jc = lane * 4;
    float4 acc[G];
#pragma unroll
    for (int g = 0; g < G; g++) acc[g] = make_float4(0.f, 0.f, 0.f, 0.f);
#pragma unroll 4
    for (int i4 = 0; i4 < H / 4; i4++) {
        float4 w0r = *(const float4*)(wk + (i4 * 4 + 0) * H + jc);
        float4 w1r = *(const float4*)(wk + (i4 * 4 + 1) * H + jc);
        float4 w2r = *(const float4*)(wk + (i4 * 4 + 2) * H + jc);
        float4 w3r = *(const float4*)(wk + (i4 * 4 + 3) * H + jc);
#pragma unroll
        for (int g = 0; g < G; g++) {
            float4 xv = *(const float4*)&xf[g][k][i4 * 4];
            fma4(acc[g], xv.x, w0r);
            fma4(acc[g], xv.y, w1r);
            fma4(acc[g], xv.z, w2r);
            fma4(acc[g], xv.w, w3r);
        }
    }
#pragma unroll
    for (int g = 0; g < G; g++) *(float4*)&of[g][k][jc] = acc[g];
}

// P = of@Ws, Q = of@Wn    (one warp per item g, all 8 modes)
__device__ __forceinline__ void pq_gemm(const float (*of)[MODES][H],
                                        float (*P)[MODES][H], float (*Q)[MODES][H],
                                        const float* __restrict__ Ws,
                                        const float* __restrict__ Wn,
                                        int warp, int lane) {
    const int g = warp;
    const int jc = lane * 4;
    float4 ap[MODES], aq[MODES];
#pragma unroll
    for (int k = 0; k < MODES; k++) {
        ap[k] = make_float4(0.f, 0.f, 0.f, 0.f);
        aq[k] = make_float4(0.f, 0.f, 0.f, 0.f);
    }
#pragma unroll 2
    for (int i4 = 0; i4 < H / 4; i4++) {
        float4 ws[4], wn[4];
#pragma unroll
        for (int ii = 0; ii < 4; ii++) {
            ws[ii] = *(const float4*)(Ws + (i4 * 4 + ii) * H + jc);
            wn[ii] = *(const float4*)(Wn + (i4 * 4 + ii) * H + jc);
        }
#pragma unroll
        for (int k = 0; k < MODES; k++) {
            float4 ov = *(const float4*)&of[g][k][i4 * 4];
            fma4(ap[k], ov.x, ws[0]); fma4(aq[k], ov.x, wn[0]);
            fma4(ap[k], ov.y, ws[1]); fma4(aq[k], ov.y, wn[1]);
            fma4(ap[k], ov.z, ws[2]); fma4(aq[k], ov.z, wn[2]);
            fma4(ap[k], ov.w, ws[3]); fma4(aq[k], ov.w, wn[3]);
        }
    }
#pragma unroll
    for (int k = 0; k < MODES; k++) {
        *(float4*)&P[g][k][jc] = ap[k];
        *(float4*)&Q[g][k][jc] = aq[k];
    }
}

// Row-streamed: o[n,:] = U8[n]@P + A8[n]@Q + b ; LayerNorm; ReLU;
// then either accumulate xf_next = U8^T @ h, or project to output.
template <bool FINAL>
__device__ __forceinline__ void expand_ln(SmemLayout& S,
                                          const float (*P)[MODES][H],
                                          const float (*Q)[MODES][H],
                                          const float* __restrict__ bsum,
                                          const float* __restrict__ gam,
                                          const float* __restrict__ bet,
                                          float (*xfout)[MODES][H],
                                          float* __restrict__ outg,
                                          int warp, int lane) {
    const int g = warp;
    const int jc = lane * 4;
    float4 preg[MODES], qreg[MODES], acc2[MODES];
#pragma unroll
    for (int k = 0; k < MODES; k++) {
        preg[k] = *(const float4*)&P[g][k][jc];
        qreg[k] = *(const float4*)&Q[g][k][jc];
        acc2[k] = make_float4(0.f, 0.f, 0.f, 0.f);
    }
    const float4 bv  = *(const float4*)&bsum[jc];
    const float4 gv  = *(const float4*)&gam[jc];
    const float4 bev = *(const float4*)&bet[jc];
    float4 bo0 = *(const float4*)&S.s_bo[0];
    float4 bo1 = *(const float4*)&S.s_bo[4];

    for (int n = 0; n < NNODE; n++) {
        float4 u0 = *(const float4*)&S.sU8[n][0];
        float4 u1 = *(const float4*)&S.sU8[n][4];
        float4 a0 = *(const float4*)&S.sA8[n][0];
        float4 a1 = *(const float4*)&S.sA8[n][4];
        float4 v = bv;
        fma4(v, u0.x, preg[0]); fma4(v, u0.y, preg[1]);
        fma4(v, u0.z, preg[2]); fma4(v, u0.w, preg[3]);
        fma4(v, u1.x, preg[4]); fma4(v, u1.y, preg[5]);
        fma4(v, u1.z, preg[6]); fma4(v, u1.w, preg[7]);
        fma4(v, a0.x, qreg[0]); fma4(v, a0.y, qreg[1]);
        fma4(v, a0.z, qreg[2]); fma4(v, a0.w, qreg[3]);
        fma4(v, a1.x, qreg[4]); fma4(v, a1.y, qreg[5]);
        fma4(v, a1.z, qreg[6]); fma4(v, a1.w, qreg[7]);

        float sm = v.x + v.y + v.z + v.w;
        float sq = v.x * v.x + v.y * v.y + v.z * v.z + v.w * v.w;
#pragma unroll
        for (int off = 16; off > 0; off >>= 1) {
            sm += __shfl_xor_sync(0xffffffffu, sm, off);
            sq += __shfl_xor_sync(0xffffffffu, sq, off);
        }
        const float mu  = sm * (1.0f / H);
        const float var = sq * (1.0f / H) - mu * mu;
        const float rs  = rsqrtf(var + 1e-5f);
        float4 h;
        h.x = fmaxf(fmaf((v.x - mu) * rs, gv.x, bev.x), 0.f);
        h.y = fmaxf(fmaf((v.y - mu) * rs, gv.y, bev.y), 0.f);
        h.z = fmaxf(fmaf((v.z - mu) * rs, gv.z, bev.z), 0.f);
        h.w = fmaxf(fmaf((v.w - mu) * rs, gv.w, bev.w), 0.f);

        if (!FINAL) {
            fma4(acc2[0], u0.x, h); fma4(acc2[1], u0.y, h);
            fma4(acc2[2], u0.z, h); fma4(acc2[3], u0.w, h);
            fma4(acc2[4], u1.x, h); fma4(acc2[5], u1.y, h);
            fma4(acc2[6], u1.z, h); fma4(acc2[7], u1.w, h);
        } else {
            float4 po0 = make_float4(0.f, 0.f, 0.f, 0.f);
            float4 po1 = make_float4(0.f, 0.f, 0.f, 0.f);
            float4 wa, wb;
            wa = *(const float4*)&S.sWo[(jc + 0) * FPN];
            wb = *(const float4*)&S.sWo[(jc + 0) * FPN + 4];
            fma4(po0, h.x, wa); fma4(po1, h.x, wb);
            wa = *(const float4*)&S.sWo[(jc + 1) * FPN];
            wb = *(const float4*)&S.sWo[(jc + 1) * FPN + 4];
            fma4(po0, h.y, wa); fma4(po1, h.y, wb);
            wa = *(const float4*)&S.sWo[(jc + 2) * FPN];
            wb = *(const float4*)&S.sWo[(jc + 2) * FPN + 4];
            fma4(po0, h.z, wa); fma4(po1, h.z, wb);
            wa = *(const float4*)&S.sWo[(jc + 3) * FPN];
            wb = *(const float4*)&S.sWo[(jc + 3) * FPN + 4];
            fma4(po0, h.w, wa); fma4(po1, h.w, wb);
#pragma unroll
            for (int off = 16; off > 0; off >>= 1) {
                po0.x += __shfl_xor_sync(0xffffffffu, po0.x, off);
                po0.y += __shfl_xor_sync(0xffffffffu, po0.y, off);
                po0.z += __shfl_xor_sync(0xffffffffu, po0.z, off);
                po0.w += __shfl_xor_sync(0xffffffffu, po0.w, off);
                po1.x += __shfl_xor_sync(0xffffffffu, po1.x, off);
                po1.y += __shfl_xor_sync(0xffffffffu, po1.y, off);
                po1.z += __shfl_xor_sync(0xffffffffu, po1.z, off);
                po1.w += __shfl_xor_sync(0xffffffffu, po1.w, off);
            }
            if (lane == 0) {
                float4 r0 = make_float4(po0.x + bo0.x, po0.y + bo0.y,
                                        po0.z + bo0.z, po0.w + bo0.w);
                float4 r1 = make_float4(po1.x + bo1.x, po1.y + bo1.y,
                                        po1.z + bo1.z, po1.w + bo1.w);
                *(float4*)&outg[(size_t)g * (NNODE * FPN) + n * FPN]     = r0;
                *(float4*)&outg[(size_t)g * (NNODE * FPN) + n * FPN + 4] = r1;
            }
        }
    }
    if (!FINAL) {
#pragma unroll
        for (int k = 0; k < MODES; k++) *(float4*)&xfout[g][k][jc] = acc2[k];
    }
}

// ---------------- main fused kernel ----------------
__global__ __launch_bounds__(NTHREADS, 1) void fused_kernel(
    const float* __restrict__ x, const float* __restrict__ U,
    const float* __restrict__ Wp, const float* __restrict__ bp,
    const float* __restrict__ Ws1, const float* __restrict__ bs1,
    const float* __restrict__ Wn1, const float* __restrict__ bn1,
    const float* __restrict__ g1, const float* __restrict__ be1,
    const float* __restrict__ Ws3, const float* __restrict__ bs3,
    const float* __restrict__ Wn3, const float* __restrict__ bn3,
    const float* __restrict__ g3, const float* __restrict__ be3,
    const float* __restrict__ Wo, const float* __restrict__ bo,
    float* __restrict__ out) {
    extern __shared__ __align__(16) float smem_raw[];
    SmemLayout& S = *reinterpret_cast<SmemLayout*>(smem_raw);
    const int tid  = threadIdx.x;
    const int lane = tid & 31;
    const int warp = tid >> 5;
    const int item0 = blockIdx.x * G;

    // ---- S0: load constants + x ----
    for (int o = tid; o < NNODE * MODES; o += NTHREADS) {
        int n = o >> 3, k = o & 7;
        S.sU8[n][k] = U[n * NNODE + k];
        (&S.sA8[0][0])[o] = g_A8[o];
    }
    for (int o = tid; o < FPN * H; o += NTHREADS) {
        S.sWp[o] = Wp[o];
        S.sWo[o] = Wo[o];
    }
    if (tid < H) {
        S.s_bp[tid] = bp[tid];
        S.s_b1[tid] = bs1[tid] + bn1[tid];
        S.s_g1[tid] = g1[tid];  S.s_be1[tid] = be1[tid];
        S.s_b3[tid] = bs3[tid] + bn3[tid];
        S.s_g3[tid] = g3[tid];  S.s_be3[tid] = be3[tid];
    }
    if (tid < MODES) S.s_s[tid] = g_s[tid];
    if (tid < FPN)   S.s_bo[tid] = bo[tid];
    {
        const float* xg = x + (size_t)item0 * (NNODE * FPN);
        for (int o = tid; o < G * NNODE * FPN; o += NTHREADS)
            (&S.sX[0][0])[o] = xg[o];
    }
    __syncthreads();

    // ---- S2: xs[g,k,f] = sum_n U8[n,k] * x[g,n,f]  (tiny) ----
    for (int o = tid; o < G * MODES * FPN; o += NTHREADS) {
        int g = o >> 6, k = (o >> 3) & 7, f = o & 7;
        float a = 0.f;
#pragma unroll 8
        for (int n = 0; n < NNODE; n++) a += S.sU8[n][k] * S.sX[g][n * FPN + f];
        S.sXS[g][k][f] = a;
    }
    __syncthreads();

    // ---- S3: xf0[g,k,j] = xs[g,k,:]@Wp + s[k]*bp[j] ----
    {
        const int g = warp, jc = lane * 4;
#pragma unroll
        for (int k = 0; k < MODES; k++) {
            const float sk = S.s_s[k];
            const float4 bpv = *(const float4*)&S.s_bp[jc];
            float4 acc = make_float4(sk * bpv.x, sk * bpv.y, sk * bpv.z, sk * bpv.w);
#pragma unroll
            for (int f = 0; f < FPN; f++) {
                const float xv = S.sXS[g][k][f];
                const float4 w = *(const float4*)&S.sWp[f * H + jc];
                fma4(acc, xv, w);
            }
            *(float4*)&S.bufA[g][k][jc] = acc;
        }
    }
    __syncthreads();

    // ---- layer 0 spectral mix ----
    mode_mix(S.bufA, S.bufB, g_w0t, warp, lane);
    __syncthreads();
    // ---- layer 1 graph conv (rank-8) ----
    pq_gemm(S.bufB, S.bufP, S.bufQ, Ws1, Wn1, warp, lane);
    __syncthreads();
    expand_ln<false>(S, S.bufP, S.bufQ, S.s_b1, S.s_g1, S.s_be1,
                     S.bufA, nullptr, warp, lane);
    __syncthreads();
    // ---- layer 2 spectral mix ----
    mode_mix(S.bufA, S.bufB, g_w2t, warp, lane);
    __syncthreads();
    // ---- layer 3 graph conv (rank-8) + output projection ----
    pq_gemm(S.bufB, S.bufP, S.bufQ, Ws3, Wn3, warp, lane);
    __syncthreads();
    expand_ln<true>(S, S.bufP, S.bufQ, S.s_b3, S.s_g3, S.s_be3,
                    nullptr, out + (size_t)item0 * (NNODE * FPN), warp, lane);
}

// ---------------- launch ----------------
extern "C" void kernel_launch(void* const* d_in, const int* in_sizes, int n_in,
                              void* d_out, int out_size) {
    const float* x   = (const float*)d_in[0];
    const float* adj = (const float*)d_in[1];
    const float* U   = (const float*)d_in[2];
    const float* Wp  = (const float*)d_in[3];
    const float* bp  = (const float*)d_in[4];
    const float* w0  = (const float*)d_in[5];
    const float* w2  = (const float*)d_in[6];
    const float* Ws1 = (const float*)d_in[7];
    const float* bs1 = (const float*)d_in[8];
    const float* Wn1 = (const float*)d_in[9];
    const float* bn1 = (const float*)d_in[10];
    const float* g1  = (const float*)d_in[11];
    const float* be1 = (const float*)d_in[12];
    const float* Ws3 = (const float*)d_in[13];
    const float* bs3 = (const float*)d_in[14];
    const float* Wn3 = (const float*)d_in[15];
    const float* bn3 = (const float*)d_in[16];
    const float* g3  = (const float*)d_in[17];
    const float* be3 = (const float*)d_in[18];
    const float* Wo  = (const float*)d_in[19];
    const float* bo  = (const float*)d_in[20];
    float* out = (float*)d_out;

    cudaFuncSetAttribute(fused_kernel, cudaFuncAttributeMaxDynamicSharedMemorySize,
                         (int)sizeof(SmemLayout));

    prep_w<<<256, 256>>>(w0, w2);
    prep_graph<<<1, 512>>>(adj, U);
    fused_kernel<<<BT / G, NTHREADS, sizeof(SmemLayout)>>>(
        x, U, Wp, bp, Ws1, bs1, Wn1, bn1, g1, be1,
        Ws3, bs3, Wn3, bn3, g3, be3, Wo, bo, out);
}

// round 3
// speedup vs baseline: 1.0628x; 1.0628x over previous
#include <cuda_runtime.h>

#define G       8
#define NNODE   64
#define FPN     8
#define H       128
#define MODES   8
#define BT      16384
#define NTHREADS 256

typedef unsigned long long u64;

// -------- persistent scratch --------
__device__ __align__(16) float g_w0t[MODES * H * H];  // [k][i][j]
__device__ __align__(16) float g_w2t[MODES * H * H];
__device__ __align__(16) float g_A8[NNODE * MODES];   // adj @ U8
__device__ float g_s[MODES];                          // colsum U8

// -------- f32x2 helpers --------
__device__ __forceinline__ u64 pks(float a) {
    u64 r; asm("mov.b64 %0,{%1,%1};" : "=l"(r) : "f"(a)); return r;
}
__device__ __forceinline__ void fma2(u64& d, u64 a, u64 b) {
    asm("fma.rn.f32x2 %0,%1,%2,%0;" : "+l"(d) : "l"(a), "l"(b));
}
__device__ __forceinline__ float2 up2(u64 a) {
    float2 r; asm("mov.b64 {%0,%1},%2;" : "=f"(r.x), "=f"(r.y) : "l"(a)); return r;
}

struct SmemLayout {
    float bufA[G][MODES][H];
    float bufB[G][MODES][H];
    float bufP[G][MODES][H];
    float bufQ[G][MODES][H];
    float WS[2][32][H];        // pq weight staging chunk (32KB)
    float sX[G][NNODE * FPN];
    float sXS[G][MODES][FPN];
    float sU8[NNODE][MODES];
    float sA8[NNODE][MODES];
    float sWp[FPN * H];
    float sWo[H * FPN];
    float s_bp[H];
    float s_b1[H]; float s_g1[H]; float s_be1[H];
    float s_b3[H]; float s_g3[H]; float s_be3[H];
    float s_s[MODES]; float s_bo[FPN];
};

__device__ __forceinline__ void fma4(float4& a, float s, const float4 b) {
    a.x = fmaf(s, b.x, a.x); a.y = fmaf(s, b.y, a.y);
    a.z = fmaf(s, b.z, a.z); a.w = fmaf(s, b.w, a.w);
}

// ---------------- single prep kernel ----------------
__global__ void prep_all(const float* __restrict__ w0, const float* __restrict__ w2,
                         const float* __restrict__ adj, const float* __restrict__ Uin) {
    const int total = MODES * H * H;
    for (int o = blockIdx.x * blockDim.x + threadIdx.x; o < total;
         o += gridDim.x * blockDim.x) {
        int k = o >> 14;
        int rem = o & 16383;
        int i = rem >> 7;
        int j = rem & 127;
        int src = ((i << 7) + j) * MODES + k;
        g_w0t[o] = w0[src];
        g_w2t[o] = w2[src];
    }
    if (blockIdx.x == 0) {
        int o = threadIdx.x;
        for (int e = o; e < NNODE * MODES; e += blockDim.x) {
            int n = e >> 3, k = e & 7;
            float a = 0.f;
            for (int m = 0; m < NNODE; m++) a += adj[n * NNODE + m] * Uin[m * NNODE + k];
            g_A8[e] = a;
        }
        if (o < MODES) {
            float s = 0.f;
            for (int m = 0; m < NNODE; m++) s += Uin[m * NNODE + o];
            g_s[o] = s;
        }
    }
}

// ---------------- stages ----------------
// of[g,k,j] = sum_i xf[g,k,i] * wt[k][i][j]   (warp = mode k; f32x2 over j-pairs)
__device__ __forceinline__ void mode_mix(const float (*xf)[MODES][H],
                                         float (*of)[MODES][H],
                                         const float* __restrict__ wt,
                                         int warp, int lane) {
    const int k = warp;
    const float* wk = wt + k * (H * H);
    const int jc = lane * 4;
    u64 a0[G], a1[G];
#pragma unroll
    for (int g = 0; g < G; g++) { a0[g] = 0ull; a1[g] = 0ull; }
#pragma unroll 4
    for (int i4 = 0; i4 < H / 4; i4++) {
        float4 xv[G];
#pragma unroll
        for (int g = 0; g < G; g++) xv[g] = *(const float4*)&xf[g][k][i4 * 4];
#pragma unroll
        for (int ii = 0; ii < 4; ii++) {
            ulonglong2 w = *(const ulonglong2*)(wk + (i4 * 4 + ii) * H + jc);
#pragma unroll
            for (int g = 0; g < G; g++) {
                const float* c = &xv[g].x;
                u64 xs = pks(c[ii]);
                fma2(a0[g], xs, w.x);
                fma2(a1[g], xs, w.y);
            }
        }
    }
#pragma unroll
    for (int g = 0; g < G; g++) {
        ulonglong2 r; r.x = a0[g]; r.y = a1[g];
        *(ulonglong2*)&of[g][k][jc] = r;
    }
}

// P = of@Ws, Q = of@Wn  (warp = item g; weights staged through smem chunks)
__device__ void pq_gemm_staged(SmemLayout& S, const float (*of)[MODES][H],
                               float (*P)[MODES][H], float (*Q)[MODES][H],
                               const float* __restrict__ Ws,
                               const float* __restrict__ Wn,
                               int warp, int lane, int tid) {
    const int g = warp;
    const int jc = lane * 4;
    u64 ap0[MODES], ap1[MODES], aq0[MODES], aq1[MODES];
#pragma unroll
    for (int k = 0; k < MODES; k++) { ap0[k] = ap1[k] = aq0[k] = aq1[k] = 0ull; }

    for (int c = 0; c < 4; c++) {
        __syncthreads();
        // coop-load 32 rows of Ws and Wn (float4 per thread x16)
        {
            const float4* ws4 = (const float4*)(Ws + c * 32 * H);
            const float4* wn4 = (const float4*)(Wn + c * 32 * H);
            float4* d0 = (float4*)&S.WS[0][0][0];
            float4* d1 = (float4*)&S.WS[1][0][0];
#pragma unroll
            for (int t = 0; t < 4; t++) {
                int o = tid + t * NTHREADS;
                d0[o] = ws4[o];
                d1[o] = wn4[o];
            }
        }
        __syncthreads();
#pragma unroll
        for (int i4 = 0; i4 < 8; i4++) {
            float4 ov[MODES];
#pragma unroll
            for (int k = 0; k < MODES; k++)
                ov[k] = *(const float4*)&of[g][k][c * 32 + i4 * 4];
#pragma unroll
            for (int ii = 0; ii < 4; ii++) {
                ulonglong2 ws = *(const ulonglong2*)&S.WS[0][i4 * 4 + ii][jc];
                ulonglong2 wn = *(const ulonglong2*)&S.WS[1][i4 * 4 + ii][jc];
#pragma unroll
                for (int k = 0; k < MODES; k++) {
                    const float* cv = &ov[k].x;
                    u64 xs = pks(cv[ii]);
                    fma2(ap0[k], xs, ws.x); fma2(ap1[k], xs, ws.y);
                    fma2(aq0[k], xs, wn.x); fma2(aq1[k], xs, wn.y);
                }
            }
        }
    }
#pragma unroll
    for (int k = 0; k < MODES; k++) {
        ulonglong2 rp; rp.x = ap0[k]; rp.y = ap1[k];
        ulonglong2 rq; rq.x = aq0[k]; rq.y = aq1[k];
        *(ulonglong2*)&P[g][k][jc] = rp;
        *(ulonglong2*)&Q[g][k][jc] = rq;
    }
}

// o[n,:] = U8[n]@P + A8[n]@Q + b ; LN ; ReLU ; then U8^T@h or output proj
template <bool FINAL>
__device__ __forceinline__ void expand_ln(SmemLayout& S,
                                          const float (*Pb)[MODES][H],
                                          const float (*Qb)[MODES][H],
                                          const float* __restrict__ bsum,
                                          const float* __restrict__ gam,
                                          const float* __restrict__ bet,
                                          float (*xfout)[MODES][H],
                                          float* __restrict__ outg,
                                          int warp, int lane) {
    const int g = warp;
    const int jc = lane * 4;
    u64 p0[MODES], p1[MODES], q0[MODES], q1[MODES], c0[MODES], c1[MODES];
#pragma unroll
    for (int k = 0; k < MODES; k++) {
        ulonglong2 tp = *(const ulonglong2*)&Pb[g][k][jc];
        ulonglong2 tq = *(const ulonglong2*)&Qb[g][k][jc];
        p0[k] = tp.x; p1[k] = tp.y; q0[k] = tq.x; q1[k] = tq.y;
        c0[k] = 0ull; c1[k] = 0ull;
    }
    const ulonglong2 bv = *(const ulonglong2*)&bsum[jc];
    const float4 gv  = *(const float4*)&gam[jc];
    const float4 bev = *(const float4*)&bet[jc];
    float4 bo0, bo1;
    if (FINAL) { bo0 = *(const float4*)&S.s_bo[0]; bo1 = *(const float4*)&S.s_bo[4]; }

    for (int n = 0; n < NNODE; n++) {
        float4 u0 = *(const float4*)&S.sU8[n][0];
        float4 u1 = *(const float4*)&S.sU8[n][4];
        float4 a0 = *(const float4*)&S.sA8[n][0];
        float4 a1 = *(const float4*)&S.sA8[n][4];
        u64 up[MODES];
        up[0] = pks(u0.x); up[1] = pks(u0.y); up[2] = pks(u0.z); up[3] = pks(u0.w);
        up[4] = pks(u1.x); up[5] = pks(u1.y); up[6] = pks(u1.z); up[7] = pks(u1.w);
        u64 v0 = bv.x, v1 = bv.y;
#pragma unroll
        for (int k = 0; k < MODES; k++) { fma2(v0, up[k], p0[k]); fma2(v1, up[k], p1[k]); }
        {
            u64 t;
            t = pks(a0.x); fma2(v0, t, q0[0]); fma2(v1, t, q1[0]);
            t = pks(a0.y); fma2(v0, t, q0[1]); fma2(v1, t, q1[1]);
            t = pks(a0.z); fma2(v0, t, q0[2]); fma2(v1, t, q1[2]);
            t = pks(a0.w); fma2(v0, t, q0[3]); fma2(v1, t, q1[3]);
            t = pks(a1.x); fma2(v0, t, q0[4]); fma2(v1, t, q1[4]);
            t = pks(a1.y); fma2(v0, t, q0[5]); fma2(v1, t, q1[5]);
            t = pks(a1.z); fma2(v0, t, q0[6]); fma2(v1, t, q1[6]);
            t = pks(a1.w); fma2(v0, t, q0[7]); fma2(v1, t, q1[7]);
        }
        float2 va = up2(v0), vb = up2(v1);
        float sm = va.x + va.y + vb.x + vb.y;
        float sq = va.x * va.x + va.y * va.y + vb.x * vb.x + vb.y * vb.y;
#pragma unroll
        for (int off = 16; off > 0; off >>= 1) {
            sm += __shfl_xor_sync(0xffffffffu, sm, off);
            sq += __shfl_xor_sync(0xffffffffu, sq, off);
        }
        const float mu  = sm * (1.0f / H);
        const float var = sq * (1.0f / H) - mu * mu;
        const float rs  = rsqrtf(var + 1e-5f);
        float4 h;
        h.x = fmaxf(fmaf((va.x - mu) * rs, gv.x, bev.x), 0.f);
        h.y = fmaxf(fmaf((va.y - mu) * rs, gv.y, bev.y), 0.f);
        h.z = fmaxf(fmaf((vb.x - mu) * rs, gv.z, bev.z), 0.f);
        h.w = fmaxf(fmaf((vb.y - mu) * rs, gv.w, bev.w), 0.f);

        if (!FINAL) {
            u64 h0, h1;
            asm("mov.b64 %0,{%1,%2};" : "=l"(h0) : "f"(h.x), "f"(h.y));
            asm("mov.b64 %0,{%1,%2};" : "=l"(h1) : "f"(h.z), "f"(h.w));
#pragma unroll
            for (int k = 0; k < MODES; k++) { fma2(c0[k], up[k], h0); fma2(c1[k], up[k], h1); }
        } else {
            float4 po0 = make_float4(0.f, 0.f, 0.f, 0.f);
            float4 po1 = make_float4(0.f, 0.f, 0.f, 0.f);
            float4 wa, wb;
            wa = *(const float4*)&S.sWo[(jc + 0) * FPN];
            wb = *(const float4*)&S.sWo[(jc + 0) * FPN + 4];
            fma4(po0, h.x, wa); fma4(po1, h.x, wb);
            wa = *(const float4*)&S.sWo[(jc + 1) * FPN];
            wb = *(const float4*)&S.sWo[(jc + 1) * FPN + 4];
            fma4(po0, h.y, wa); fma4(po1, h.y, wb);
            wa = *(const float4*)&S.sWo[(jc + 2) * FPN];
            wb = *(const float4*)&S.sWo[(jc + 2) * FPN + 4];
            fma4(po0, h.z, wa); fma4(po1, h.z, wb);
            wa = *(const float4*)&S.sWo[(jc + 3) * FPN];
            wb = *(const float4*)&S.sWo[(jc + 3) * FPN + 4];
            fma4(po0, h.w, wa); fma4(po1, h.w, wb);
#pragma unroll
            for (int off = 16; off > 0; off >>= 1) {
                po0.x += __shfl_xor_sync(0xffffffffu, po0.x, off);
                po0.y += __shfl_xor_sync(0xffffffffu, po0.y, off);
                po0.z += __shfl_xor_sync(0xffffffffu, po0.z, off);
                po0.w += __shfl_xor_sync(0xffffffffu, po0.w, off);
                po1.x += __shfl_xor_sync(0xffffffffu, po1.x, off);
                po1.y += __shfl_xor_sync(0xffffffffu, po1.y, off);
                po1.z += __shfl_xor_sync(0xffffffffu, po1.z, off);
                po1.w += __shfl_xor_sync(0xffffffffu, po1.w, off);
            }
            if (lane == 0) {
                float4 r0 = make_float4(po0.x + bo0.x, po0.y + bo0.y,
                                        po0.z + bo0.z, po0.w + bo0.w);
                float4 r1 = make_float4(po1.x + bo1.x, po1.y + bo1.y,
                                        po1.z + bo1.z, po1.w + bo1.w);
                *(float4*)&outg[(size_t)g * (NNODE * FPN) + n * FPN]     = r0;
                *(float4*)&outg[(size_t)g * (NNODE * FPN) + n * FPN + 4] = r1;
            }
        }
    }
    if (!FINAL) {
#pragma unroll
        for (int k = 0; k < MODES; k++) {
            ulonglong2 r; r.x = c0[k]; r.y = c1[k];
            *(ulonglong2*)&xfout[g][k][jc] = r;
        }
    }
}

// ---------------- main fused kernel ----------------
__global__ __launch_bounds__(NTHREADS, 1) void fused_kernel(
    const float* __restrict__ x, const float* __restrict__ U,
    const float* __restrict__ Wp, const float* __restrict__ bp,
    const float* __restrict__ Ws1, const float* __restrict__ bs1,
    const float* __restrict__ Wn1, const float* __restrict__ bn1,
    const float* __restrict__ g1, const float* __restrict__ be1,
    const float* __restrict__ Ws3, const float* __restrict__ bs3,
    const float* __restrict__ Wn3, const float* __restrict__ bn3,
    const float* __restrict__ g3, const float* __restrict__ be3,
    const float* __restrict__ Wo, const float* __restrict__ bo,
    float* __restrict__ out) {
    extern __shared__ __align__(16) float smem_raw[];
    SmemLayout& S = *reinterpret_cast<SmemLayout*>(smem_raw);
    const int tid  = threadIdx.x;
    const int lane = tid & 31;
    const int warp = tid >> 5;
    const int item0 = blockIdx.x * G;

    // ---- prologue: constants + x ----
    for (int o = tid; o < NNODE * MODES; o += NTHREADS) {
        int n = o >> 3, k = o & 7;
        S.sU8[n][k] = U[n * NNODE + k];
        (&S.sA8[0][0])[o] = g_A8[o];
    }
    for (int o = tid; o < FPN * H; o += NTHREADS) {
        S.sWp[o] = Wp[o];
        S.sWo[o] = Wo[o];
    }
    if (tid < H) {
        S.s_bp[tid] = bp[tid];
        S.s_b1[tid] = bs1[tid] + bn1[tid];
        S.s_g1[tid] = g1[tid];  S.s_be1[tid] = be1[tid];
        S.s_b3[tid] = bs3[tid] + bn3[tid];
        S.s_g3[tid] = g3[tid];  S.s_be3[tid] = be3[tid];
    }
    if (tid < MODES) S.s_s[tid] = g_s[tid];
    if (tid < FPN)   S.s_bo[tid] = bo[tid];
    {
        const float* xg = x + (size_t)item0 * (NNODE * FPN);
        for (int o = tid; o < G * NNODE * FPN; o += NTHREADS)
            (&S.sX[0][0])[o] = xg[o];
    }
    __syncthreads();

    // ---- xs = U8^T x ----
    for (int o = tid; o < G * MODES * FPN; o += NTHREADS) {
        int g = o >> 6, k = (o >> 3) & 7, f = o & 7;
        float a = 0.f;
#pragma unroll 8
        for (int n = 0; n < NNODE; n++) a += S.sU8[n][k] * S.sX[g][n * FPN + f];
        S.sXS[g][k][f] = a;
    }
    __syncthreads();

    // ---- xf0 = xs@Wp + s*bp ----
    {
        const int g = warp, jc = lane * 4;
#pragma unroll
        for (int k = 0; k < MODES; k++) {
            const float sk = S.s_s[k];
            const float4 bpv = *(const float4*)&S.s_bp[jc];
            float4 acc = make_float4(sk * bpv.x, sk * bpv.y, sk * bpv.z, sk * bpv.w);
#pragma unroll
            for (int f = 0; f < FPN; f++) {
                const float xv = S.sXS[g][k][f];
                const float4 w = *(const float4*)&S.sWp[f * H + jc];
                fma4(acc, xv, w);
            }
            *(float4*)&S.bufA[g][k][jc] = acc;
        }
    }
    __syncthreads();

    mode_mix(S.bufA, S.bufB, g_w0t, warp, lane);
    __syncthreads();
    pq_gemm_staged(S, S.bufB, S.bufP, S.bufQ, Ws1, Wn1, warp, lane, tid);
    __syncthreads();
    expand_ln<false>(S, S.bufP, S.bufQ, S.s_b1, S.s_g1, S.s_be1,
                     S.bufA, nullptr, warp, lane);
    __syncthreads();
    mode_mix(S.bufA, S.bufB, g_w2t, warp, lane);
    __syncthreads();
    pq_gemm_staged(S, S.bufB, S.bufP, S.bufQ, Ws3, Wn3, warp, lane, tid);
    __syncthreads();
    expand_ln<true>(S, S.bufP, S.bufQ, S.s_b3, S.s_g3, S.s_be3,
                    nullptr, out + (size_t)item0 * (NNODE * FPN), warp, lane);
}

// ---------------- launch ----------------
extern "C" void kernel_launch(void* const* d_in, const int* in_sizes, int n_in,
                              void* d_out, int out_size) {
    const float* x   = (const float*)d_in[0];
    const float* adj = (const float*)d_in[1];
    const float* U   = (const float*)d_in[2];
    const float* Wp  = (const float*)d_in[3];
    const float* bp  = (const float*)d_in[4];
    const float* w0  = (const float*)d_in[5];
    const float* w2  = (const float*)d_in[6];
    const float* Ws1 = (const float*)d_in[7];
    const float* bs1 = (const float*)d_in[8];
    const float* Wn1 = (const float*)d_in[9];
    const float* bn1 = (const float*)d_in[10];
    const float* g1  = (const float*)d_in[11];
    const float* be1 = (const float*)d_in[12];
    const float* Ws3 = (const float*)d_in[13];
    const float* bs3 = (const float*)d_in[14];
    const float* Wn3 = (const float*)d_in[15];
    const float* bn3 = (const float*)d_in[16];
    const float* g3  = (const float*)d_in[17];
    const float* be3 = (const float*)d_in[18];
    const float* Wo  = (const float*)d_in[19];
    const float* bo  = (const float*)d_in[20];
    float* out = (float*)d_out;

    cudaFuncSetAttribute(fused_kernel, cudaFuncAttributeMaxDynamicSharedMemorySize,
                         (int)sizeof(SmemLayout));

    prep_all<<<256, 256>>>(w0, w2, adj, U);
    fused_kernel<<<BT / G, NTHREADS, sizeof(SmemLayout)>>>(
        x, U, Wp, bp, Ws1, bs1, Wn1, bn1, g1, be1,
        Ws3, bs3, Wn3, bn3, g3, be3, Wo, bo, out);
}